// round 13
// baseline (speedup 1.0000x reference)
#include <cuda_runtime.h>

// Signature-kernel MMD. R12 base (fp32 folded table 0.25*inc-1, stride 63,
// 15904 B/task, WPC=2 -> 7 CTAs/SM, guard-only zeroing) with the PDE cells
// packed as f32x2 pairs (k0,k2)/(k1,k3): 8 scalar FMA/FADD -> 4 FFMA2 + 4
// FADD2, bit-identical element-wise fp32. Lane-0 boundary now emerges from
// zeroed shfl inputs (no predicated writes on packed values).

#define BSZ 32
#define LEN 64
#define NTRI ((BSZ*(BSZ+1))/2)     // 528
#define NTASKS (2*NTRI + BSZ*BSZ)  // 2080
#define WPC 2
#define NBLK (NTASKS / WPC)        // 1040

#define RSF 63                     // row stride in floats
#define GUARDF 4
#define OSZF (31*RSF)              // 1953
#define WFLOATS 3976               // 15904 B per task

__device__ float g_partial[NTASKS];
__device__ unsigned int g_count;   // zero-init; reducer re-arms

typedef unsigned long long u64;

__device__ __forceinline__ u64 pk(float lo, float hi) {
    u64 r; asm("mov.b64 %0, {%1,%2};" : "=l"(r) : "f"(lo), "f"(hi)); return r;
}
__device__ __forceinline__ void upk(u64 p, float& lo, float& hi) {
    asm("mov.b64 {%0,%1}, %2;" : "=f"(lo), "=f"(hi) : "l"(p));
}
__device__ __forceinline__ u64 fma2(u64 a, u64 b, u64 c) {
    u64 r; asm("fma.rn.f32x2 %0, %1, %2, %3;" : "=l"(r) : "l"(a), "l"(b), "l"(c));
    return r;
}
__device__ __forceinline__ u64 add2(u64 a, u64 b) {
    u64 r; asm("add.rn.f32x2 %0, %1, %2;" : "=l"(r) : "l"(a), "l"(b)); return r;
}

__global__ void __launch_bounds__(32*WPC, 7)
sig_kernel(const float* __restrict__ x, const float* __restrict__ y,
           float* __restrict__ out)
{
    extern __shared__ __align__(16) float smem[];
    const int lane = threadIdx.x & 31;
    const int wid  = threadIdx.x >> 5;
    const int task = blockIdx.x * WPC + wid;

    float* warpbase = smem + wid * WFLOATS;
    float* Ob = warpbase + GUARDF;        // odd coarse rows 1,3,..,61
    float* Eb = Ob + OSZF;                // even coarse rows 0,2,..,62

    // Zero ONLY guard + tail pad (all other PDE-readable bytes gram-written).
    if (lane == 0) {
        reinterpret_cast<uint4*>(warpbase)[0]   = make_uint4(0u,0u,0u,0u);
        reinterpret_cast<uint4*>(warpbase)[993] = make_uint4(0u,0u,0u,0u);
    }

    // ---- decode task -> pair pointers + weight ----
    const float *pa, *pb;
    float weight;
    {
        int t = task;
        if (t < 2*NTRI) {
            const float* base = (t < NTRI) ? x : y;
            if (t >= NTRI) t -= NTRI;
            int a = 0;
            while (t >= (BSZ - a)) { t -= (BSZ - a); ++a; }
            int b = a + t;
            pa = base + a*(LEN*4);
            pb = base + b*(LEN*4);
            weight = (a == b ? 1.0f : 2.0f) * (1.0f/1024.0f);
        } else {
            t -= 2*NTRI;
            pa = x + (t >> 5)*(LEN*4);
            pb = y + (t & 31)*(LEN*4);
            weight = -2.0f/1024.0f;
        }
    }

    // ---- streaming RBF gram + folded second differences (fp32) ----
    const int j0 = lane << 1;
    const float4 b0 = __ldg(reinterpret_cast<const float4*>(pb + 4*j0));
    const float4 b1 = __ldg(reinterpret_cast<const float4*>(pb + 4*j0 + 4));

    float g0p, g1p;
    {
        float4 a = __ldg(reinterpret_cast<const float4*>(pa));
        float d0x=a.x-b0.x, d0y=a.y-b0.y, d0z=a.z-b0.z, d0w=a.w-b0.w;
        float d1x=a.x-b1.x, d1y=a.y-b1.y, d1z=a.z-b1.z, d1w=a.w-b1.w;
        g0p = __expf(-0.5f*(d0x*d0x + d0y*d0y + d0z*d0z + d0w*d0w));
        g1p = __expf(-0.5f*(d1x*d1x + d1y*d1y + d1z*d1z + d1w*d1w));
    }
    #pragma unroll 4
    for (int u = 1; u < LEN; ++u) {
        float4 a = __ldg(reinterpret_cast<const float4*>(pa + 4*u));
        float d0x=a.x-b0.x, d0y=a.y-b0.y, d0z=a.z-b0.z, d0w=a.w-b0.w;
        float d1x=a.x-b1.x, d1y=a.y-b1.y, d1z=a.z-b1.z, d1w=a.w-b1.w;
        float g0 = __expf(-0.5f*(d0x*d0x + d0y*d0y + d0z*d0z + d0w*d0w));
        float g1 = __expf(-0.5f*(d1x*d1x + d1y*d1y + d1z*d1z + d1w*d1w));
        float t0 = g0 - g0p;
        float t1 = g1 - g1p;
        float tn = __shfl_down_sync(0xffffffffu, t0, 1);
        float r0 = fmaf(0.25f, t1 - t0, -1.0f);
        float r1 = fmaf(0.25f, tn - t1, -1.0f);
        int v = u - 1;
        float* row = ((v & 1) ? Ob : Eb) + (v >> 1) * RSF;
        row[j0] = r0;
        if (lane != 31) row[j0 + 1] = r1;
        g0p = g0; g1p = g1;
    }
    __syncwarp();

    // ---- Goursat PDE, packed f32x2 wavefront ----
    // Pairs: PA0={A0,A2}, PB0={B0,B2}, PB1={B1,B3}; carried scalars A1s,B1s,B3s.
    // Lane-0 boundary: sh1/sh1b forced to 0 => K[0,*]=1 emerges (v0=B0, w0=v0).
    const int L = lane;
    const bool isL0 = (L == 0);
    const float* p0 = (L == 0) ? Ob : (Ob + 61*L - 63);
    const float* p1 = Eb + 61*L;
    const float* p3 = Ob + 61*L - 1;

    const float one0 = isL0 ? 1.f : 0.f;
    u64 PA0 = pk(one0, 0.f);      // {A0, A2} diag 0
    u64 PB0 = pk(one0, 0.f);      // {B0, B2} diag 1
    u64 PB1 = pk(one0, 0.f);      // {B1, B3} diag 1
    float A1s = 0.f, B1s = one0, B3s = 0.f;

    float a0A = p0[0];
    float a2s = p1[-1];           // p2[0] == p1[-1]
    float sh2 = 0.0f;

    #pragma unroll 5
    for (int m = 0; m < 125; ++m) {
        float sh1 = __shfl_up_sync(0xffffffffu, B3s, 1);
        if (isL0) sh1 = 0.f;
        float a0B = p0[m+1];
        float a1  = p1[m];
        float a3  = p3[m];
        // diag d = 2m+2:  v0=sh2*a0A+sh1+B0, v2=A1*a2+B1+B2 | v1=A0*a1+B0+B1, v3=A2*a3+B2+B3
        u64 Z1  = pk(sh1, B1s);
        u64 Pv0 = add2(fma2(pk(sh2, A1s), pk(a0A, a2s), Z1), PB0);
        u64 Y2  = pk(a1, a3);
        u64 Pv1 = add2(fma2(PA0, Y2, PB0), PB1);
        float v1s, v3s; upk(Pv1, v1s, v3s);
        // diag d+1 = 2m+3
        float sh1b = __shfl_up_sync(0xffffffffu, v3s, 1);
        if (isL0) sh1b = 0.f;
        u64 Pw0 = add2(fma2(Z1, pk(a0B, a1), pk(sh1b, v1s)), Pv0);
        u64 Pw1 = add2(fma2(PB0, Y2, Pv0), Pv1);
        float w1s, w3s; upk(Pw1, w1s, w3s);
        // rotate (stays packed)
        PA0 = Pv0; PB0 = Pw0; PB1 = Pw1;
        A1s = v1s; B1s = w1s; B3s = w3s;
        a0A = a0B; a2s = a1; sh2 = sh1b;
    }
    // final diag 252: cell k=2 on lane 31 (i=126, j=126); inc = carried a2s.
    float b0lo, B2s; upk(PB0, b0lo, B2s);
    float f2 = fmaf(A1s, a2s, B1s) + B2s;
    float res = __shfl_sync(0xffffffffu, f2, 31);
    if (lane == 0) g_partial[task] = res * weight;

    // ---- last-block deterministic reduction (dynamic smem only) ----
    __threadfence();
    __syncthreads();
    unsigned int* ticket_slot = reinterpret_cast<unsigned int*>(smem);
    if (threadIdx.x == 0) *ticket_slot = atomicAdd(&g_count, 1u);
    __syncthreads();
    if (*ticket_slot == (unsigned)(gridDim.x - 1)) {
        double s = 0.0;
        for (int i = threadIdx.x; i < NTASKS; i += 32*WPC)
            s += (double)__ldcg(&g_partial[i]);
        double* ds = reinterpret_cast<double*>(smem + 64);
        ds[threadIdx.x] = s;
        __syncthreads();
        for (int w = (32*WPC)/2; w > 0; w >>= 1) {
            if (threadIdx.x < w) ds[threadIdx.x] += ds[threadIdx.x + w];
            __syncthreads();
        }
        if (threadIdx.x == 0) {
            out[0] = (float)ds[0];
            g_count = 0;                 // re-arm for next graph replay
        }
    }
}

extern "C" void kernel_launch(void* const* d_in, const int* in_sizes, int n_in,
                              void* d_out, int out_size)
{
    const float* x = (const float*)d_in[0];
    const float* y = (const float*)d_in[1];
    (void)in_sizes; (void)n_in; (void)out_size;

    cudaFuncSetAttribute(sig_kernel,
                         cudaFuncAttributePreferredSharedMemoryCarveout, 100);

    const size_t shmem = (size_t)WPC * WFLOATS * sizeof(float);  // 31808 B
    sig_kernel<<<NBLK, 32*WPC, shmem>>>(x, y, (float*)d_out);
}